// round 4
// baseline (speedup 1.0000x reference)
#include <cuda_runtime.h>
#include <math.h>

// PCEN: ema_t = w*x_t + (1-w)*ema_{t-1}, ema_0 = x_0
//       out = (x/(1e-6+ema)^a + delta)^(1/r) - delta^(1/r)
// Shapes: x [B,T,C] fp32, params [C]. B=64, T=4096, C=80.
//
// Parallelization: split T into NCHUNK chunks per (b,c) row. Each chunk
// (except chunk 0) re-runs WARM extra steps before its output region to
// converge the EMA: error ~ (1-w)^WARM = 0.96^512 ~ 8e-10 relative.

#define TB 64
#define TT 4096
#define TC 80
#define CHUNK 512
#define NCHUNK (TT / CHUNK)
#define WARM 512
#define FLOOR_C 1e-6f
#define UNROLL 16
#define BLOCK 128

__global__ void __launch_bounds__(BLOCK)
pcen_kernel(const float* __restrict__ x,
            const float* __restrict__ alpha,
            const float* __restrict__ delta,
            const float* __restrict__ root,
            const float* __restrict__ smooth,
            float* __restrict__ out)
{
    const int ROWS = TB * TC;
    int gid = blockIdx.x * BLOCK + threadIdx.x;
    if (gid >= ROWS * NCHUNK) return;

    int chunk = gid / ROWS;          // blocks are chunk-contiguous (ROWS % BLOCK == 0)
    int rc    = gid - chunk * ROWS;
    int b     = rc / TC;
    int c     = rc - b * TC;

    // Per-channel constants (uniform within thread)
    float w = fminf(fmaxf(smooth[c], 0.0f), 1.0f);
    float a = fminf(alpha[c], 1.0f);
    float r = fmaxf(root[c], 1.0f);
    float d = delta[c];
    float inv_r = 1.0f / r;
    bool  is_sqrt = (r == 2.0f);
    float dpow = is_sqrt ? sqrtf(d) : exp2f(inv_r * __log2f(d));
    float na = -a;

    int s  = chunk * CHUNK;
    int t0 = (chunk == 0) ? 0 : (s - WARM);

    const float* xp = x   + ((size_t)b * TT) * TC + c;
    float*       op = out + ((size_t)b * TT) * TC + c;

    // init EMA with first sample of (warm-up) window; the first loop update
    // is idempotent (ema + w*(x-ema) with x==ema), which also reproduces the
    // reference's ema_0 = x_0 for chunk 0.
    float ema = __ldg(xp + (size_t)t0 * TC);

    // warm-up sweep (no output)
    #pragma unroll 8
    for (int t = t0; t < s; ++t) {
        float xv = __ldg(xp + (size_t)t * TC);
        ema = fmaf(w, xv - ema, ema);
    }

    // main sweep: batch loads (MLP) then serial EMA + elementwise transform
    for (int t = s; t < s + CHUNK; t += UNROLL) {
        float xv[UNROLL];
        #pragma unroll
        for (int i = 0; i < UNROLL; ++i)
            xv[i] = __ldg(xp + (size_t)(t + i) * TC);

        #pragma unroll
        for (int i = 0; i < UNROLL; ++i) {
            ema = fmaf(w, xv[i] - ema, ema);           // w*x + (1-w)*ema
            float base = ema + FLOOR_C;
            float p = exp2f(na * __log2f(base));        // base^(-a)
            float y = fmaf(xv[i], p, d);                // x*base^(-a) + delta
            float o = is_sqrt ? sqrtf(y)
                              : exp2f(inv_r * __log2f(y));
            op[(size_t)(t + i) * TC] = o - dpow;
        }
    }
}

extern "C" void kernel_launch(void* const* d_in, const int* in_sizes, int n_in,
                              void* d_out, int out_size)
{
    const float* x      = (const float*)d_in[0];
    const float* alpha  = (const float*)d_in[1];
    const float* delta  = (const float*)d_in[2];
    const float* root   = (const float*)d_in[3];
    const float* smooth = (const float*)d_in[4];
    float* out = (float*)d_out;

    const int total = TB * TC * NCHUNK;            // 40960 threads
    dim3 grid((total + BLOCK - 1) / BLOCK);        // 320 blocks of 128
    pcen_kernel<<<grid, BLOCK>>>(x, alpha, delta, root, smooth, out);
}

// round 8
// speedup vs baseline: 1.0937x; 1.0937x over previous
#include <cuda_runtime.h>
#include <math.h>

// PCEN: ema_t = w*x_t + (1-w)*ema_{t-1}, ema_0 = x_0
//       out = (x/(1e-6+ema)^a + delta)^(1/r) - delta^(1/r)
// Shapes: x [B,T,C] fp32, params [C]. B=64, T=4096, C=80.
//
// Parallelization: T split into NCHUNK chunks of CHUNK per (b,c) row; each
// chunk (except the first) re-runs WARM extra steps to converge the EMA:
// rel error ~ (1-w)^WARM = 0.96^256 ~ 2.9e-5, far under the 1e-3 gate.
// Warm-up re-reads hit L2 (84MB input < 126MB L2), so DRAM traffic stays ~1x.

#define TB 64
#define TT 4096
#define TC 80
#define CHUNK 128
#define NCHUNK (TT / CHUNK)   // 32
#define WARM 256
#define FLOOR_C 1e-6f
#define UNROLL 8
#define BLOCK 128

__global__ void __launch_bounds__(BLOCK)
pcen_kernel(const float* __restrict__ x,
            const float* __restrict__ alpha,
            const float* __restrict__ delta,
            const float* __restrict__ root,
            const float* __restrict__ smooth,
            float* __restrict__ out)
{
    const int ROWS = TB * TC;                 // 5120
    int gid = blockIdx.x * BLOCK + threadIdx.x;

    int chunk = gid / ROWS;                   // chunk-major: warps keep consecutive c
    int rc    = gid - chunk * ROWS;
    int b     = rc / TC;
    int c     = rc - b * TC;

    // Per-channel constants
    float w = fminf(fmaxf(smooth[c], 0.0f), 1.0f);
    float a = fminf(alpha[c], 1.0f);
    float r = fmaxf(root[c], 1.0f);
    float d = delta[c];
    float inv_r = 1.0f / r;
    float dpow = exp2f(inv_r * __log2f(d));   // d > 0 in this problem
    float na = -a;

    int s  = chunk * CHUNK;
    int t0 = (chunk == 0) ? 0 : (s - WARM);

    const float* xp = x   + ((size_t)b * TT) * TC + c;
    float*       op = out + ((size_t)b * TT) * TC + c;

    // init EMA with first sample of the window; first update is idempotent,
    // which also reproduces the reference's ema_0 = x_0 for chunk 0.
    float ema = __ldg(xp + (size_t)t0 * TC);

    // warm-up sweep (no output) — mostly L2 hits
    #pragma unroll 8
    for (int t = t0; t < s; ++t) {
        float xv = __ldg(xp + (size_t)t * TC);
        ema = fmaf(w, xv - ema, ema);
    }

    // main sweep: batch loads (MLP) then serial EMA + elementwise transform
    for (int t = s; t < s + CHUNK; t += UNROLL) {
        float xv[UNROLL];
        #pragma unroll
        for (int i = 0; i < UNROLL; ++i)
            xv[i] = __ldg(xp + (size_t)(t + i) * TC);

        #pragma unroll
        for (int i = 0; i < UNROLL; ++i) {
            ema = fmaf(w, xv[i] - ema, ema);            // w*x + (1-w)*ema
            float base = ema + FLOOR_C;
            float p = exp2f(na * __log2f(base));        // base^(-a), 2x MUFU
            float y = fmaf(xv[i], p, d);                // x*base^(-a) + delta
            float o = exp2f(inv_r * __log2f(y));        // y^(1/r), 2x MUFU
            op[(size_t)(t + i) * TC] = o - dpow;
        }
    }
}

extern "C" void kernel_launch(void* const* d_in, const int* in_sizes, int n_in,
                              void* d_out, int out_size)
{
    const float* x      = (const float*)d_in[0];
    const float* alpha  = (const float*)d_in[1];
    const float* delta  = (const float*)d_in[2];
    const float* root   = (const float*)d_in[3];
    const float* smooth = (const float*)d_in[4];
    float* out = (float*)d_out;

    const int total = TB * TC * NCHUNK;        // 163840 threads
    dim3 grid(total / BLOCK);                  // 1280 blocks of 128
    pcen_kernel<<<grid, BLOCK>>>(x, alpha, delta, root, smooth, out);
}

// round 10
// speedup vs baseline: 2.1527x; 1.9683x over previous
#include <cuda_runtime.h>
#include <math.h>

// PCEN: ema_t = w*x_t + (1-w)*ema_{t-1}, ema_0 = x_0
//       out = (x/(1e-6+ema)^a + delta)^(1/r) - delta^(1/r)
// x [B,T,C] fp32, params [C]. B=64, T=4096, C=80.
//
// T split into NCHUNK chunks of CHUNK per row; chunks (except first) re-run
// WARM steps to converge the EMA (0.96^256 ~ 2.9e-5). Warm-up re-reads hit L2.
// float2 across channels: 2 independent EMA chains per thread (2x ILP),
// half the LDGs, STG.64 outputs.

#define TB 64
#define TT 4096
#define TC 80
#define C2 (TC / 2)            // 40 float2 lanes per row
#define CHUNK 128
#define NCHUNK (TT / CHUNK)    // 32
#define WARM 256
#define FLOOR_C 1e-6f
#define UNROLL 8
#define BLOCK 128

__device__ __forceinline__ float ex2(float x) { float r; asm("ex2.approx.ftz.f32 %0, %1;" : "=f"(r) : "f"(x)); return r; }
__device__ __forceinline__ float lg2(float x) { float r; asm("lg2.approx.ftz.f32 %0, %1;" : "=f"(r) : "f"(x)); return r; }
__device__ __forceinline__ float rsq(float x) { float r; asm("rsqrt.approx.ftz.f32 %0, %1;" : "=f"(r) : "f"(x)); return r; }

template <bool IS_SQRT>
__device__ __forceinline__ void main_sweep(
    const float2* __restrict__ xp, float2* __restrict__ op, int s,
    float2 ema, float wx, float wy, float nax, float nay,
    float dx, float dy, float irx, float iry, float dpx, float dpy)
{
    for (int t = s; t < s + CHUNK; t += UNROLL) {
        float2 xv[UNROLL];
        #pragma unroll
        for (int i = 0; i < UNROLL; ++i)
            xv[i] = __ldg(xp + (size_t)(t + i) * C2);

        #pragma unroll
        for (int i = 0; i < UNROLL; ++i) {
            ema.x = fmaf(wx, xv[i].x - ema.x, ema.x);
            ema.y = fmaf(wy, xv[i].y - ema.y, ema.y);
            float bx = ema.x + FLOOR_C;
            float by = ema.y + FLOOR_C;
            float px = ex2(nax * lg2(bx));        // base^(-a)
            float py = ex2(nay * lg2(by));
            float yx = fmaf(xv[i].x, px, dx);     // x*base^(-a) + delta
            float yy = fmaf(xv[i].y, py, dy);
            float ox, oy;
            if (IS_SQRT) {                         // y^(1/2) = y * rsqrt(y)
                ox = yx * rsq(yx);
                oy = yy * rsq(yy);
            } else {
                ox = ex2(irx * lg2(yx));
                oy = ex2(iry * lg2(yy));
            }
            float2 o;
            o.x = ox - dpx;
            o.y = oy - dpy;
            op[(size_t)(t + i) * C2] = o;
        }
    }
}

__global__ void __launch_bounds__(BLOCK, 8)
pcen_kernel(const float* __restrict__ x,
            const float* __restrict__ alpha,
            const float* __restrict__ delta,
            const float* __restrict__ root,
            const float* __restrict__ smooth,
            float* __restrict__ out)
{
    const int ROWS = TB * C2;                       // 2560 float2 lanes
    int gid = blockIdx.x * BLOCK + threadIdx.x;

    int chunk = gid / ROWS;                         // uniform per block (ROWS % BLOCK == 0)
    int rc    = gid - chunk * ROWS;
    int b     = rc / C2;
    int c2    = rc - b * C2;

    // Per-channel-pair constants
    float2 sm = ((const float2*)smooth)[c2];
    float2 al = ((const float2*)alpha)[c2];
    float2 rt = ((const float2*)root)[c2];
    float2 dl = ((const float2*)delta)[c2];
    float wx = fminf(fmaxf(sm.x, 0.0f), 1.0f), wy = fminf(fmaxf(sm.y, 0.0f), 1.0f);
    float nax = -fminf(al.x, 1.0f),            nay = -fminf(al.y, 1.0f);
    float rx = fmaxf(rt.x, 1.0f),              ry = fmaxf(rt.y, 1.0f);
    float irx = 1.0f / rx,                     iry = 1.0f / ry;
    float dpx = ex2(irx * lg2(dl.x));          // delta^(1/r), delta > 0 here
    float dpy = ex2(iry * lg2(dl.y));
    bool is_sqrt = (rx == 2.0f) && (ry == 2.0f);

    int s  = chunk * CHUNK;
    int t0 = (chunk == 0) ? 0 : (s - WARM);

    const float2* xp = (const float2*)(x   + ((size_t)b * TT) * TC) + c2;
    float2*       op = (float2*)      (out + ((size_t)b * TT) * TC) + c2;

    // Seed with first window sample; first update is idempotent (also exactly
    // reproduces reference ema_0 = x_0 for chunk 0).
    float2 ema = __ldg(xp + (size_t)t0 * C2);

    // Warm-up sweep (no output) — two independent FMA chains, L2-resident
    #pragma unroll 8
    for (int t = t0; t < s; ++t) {
        float2 xv = __ldg(xp + (size_t)t * C2);
        ema.x = fmaf(wx, xv.x - ema.x, ema.x);
        ema.y = fmaf(wy, xv.y - ema.y, ema.y);
    }

    if (is_sqrt)
        main_sweep<true >(xp, op, s, ema, wx, wy, nax, nay, dl.x, dl.y, irx, iry, dpx, dpy);
    else
        main_sweep<false>(xp, op, s, ema, wx, wy, nax, nay, dl.x, dl.y, irx, iry, dpx, dpy);
}

extern "C" void kernel_launch(void* const* d_in, const int* in_sizes, int n_in,
                              void* d_out, int out_size)
{
    const float* x      = (const float*)d_in[0];
    const float* alpha  = (const float*)d_in[1];
    const float* delta  = (const float*)d_in[2];
    const float* root   = (const float*)d_in[3];
    const float* smooth = (const float*)d_in[4];
    float* out = (float*)d_out;

    const int total = TB * C2 * NCHUNK;        // 81920 threads
    dim3 grid(total / BLOCK);                  // 640 blocks of 128
    pcen_kernel<<<grid, BLOCK>>>(x, alpha, delta, root, smooth, out);
}

// round 11
// speedup vs baseline: 2.4653x; 1.1452x over previous
#include <cuda_runtime.h>
#include <math.h>

// PCEN: ema_t = w*x_t + (1-w)*ema_{t-1}, ema_0 = x_0
//       out = (x/(1e-6+ema)^a + delta)^(1/r) - delta^(1/r)
// x [B,T,C] fp32, params [C]. B=64, T=4096, C=80.
//
// T split into 32 chunks of 128 per (b,c2) row; non-first chunks re-run
// WARM=256 steps to converge the EMA (0.96^256 ~ 2.9e-5 -> out err ~1.5e-4).
// Warm-up re-reads are L2-resident. float2 across channels (2 EMA chains/thread).
// This revision: deep double-buffered prefetch (UNW=16 / UNM=8), 128-reg
// budget, and ema = fmaf(1-w, ema, w*x) to halve the serial-chain latency.

#define TB 64
#define TT 4096
#define TC 80
#define C2 (TC / 2)            // 40 float2 lanes per row
#define CHUNK 128
#define NCHUNK (TT / CHUNK)    // 32
#define WARM 256
#define FLOOR_C 1e-6f
#define UNW 16                 // warm-up batch (double-buffered)
#define UNM 8                  // main batch (double-buffered)
#define BLOCK 128

__device__ __forceinline__ float ex2(float x) { float r; asm("ex2.approx.ftz.f32 %0, %1;" : "=f"(r) : "f"(x)); return r; }
__device__ __forceinline__ float lg2(float x) { float r; asm("lg2.approx.ftz.f32 %0, %1;" : "=f"(r) : "f"(x)); return r; }
__device__ __forceinline__ float rsq(float x) { float r; asm("rsqrt.approx.ftz.f32 %0, %1;" : "=f"(r) : "f"(x)); return r; }

template <bool IS_SQRT>
__device__ __forceinline__ void pcen_step(
    float2 v, float& ema_x, float& ema_y,
    float wx, float wy, float ux, float uy,
    float nax, float nay, float dx, float dy,
    float irx, float iry, float dpx, float dpy, float2& o)
{
    ema_x = fmaf(ux, ema_x, wx * v.x);        // (1-w)*ema + w*x : 4-cyc chain
    ema_y = fmaf(uy, ema_y, wy * v.y);
    float bx = ema_x + FLOOR_C;
    float by = ema_y + FLOOR_C;
    float px = ex2(nax * lg2(bx));            // base^(-a)
    float py = ex2(nay * lg2(by));
    float yx = fmaf(v.x, px, dx);             // x*base^(-a) + delta
    float yy = fmaf(v.y, py, dy);
    float ox, oy;
    if (IS_SQRT) {                            // y^(1/2) = y * rsqrt(y)
        ox = yx * rsq(yx);
        oy = yy * rsq(yy);
    } else {
        ox = ex2(irx * lg2(yx));
        oy = ex2(iry * lg2(yy));
    }
    o.x = ox - dpx;
    o.y = oy - dpy;
}

template <bool IS_SQRT>
__device__ __forceinline__ void main_sweep(
    const float2* __restrict__ pm, float2* __restrict__ po,
    float ema_x, float ema_y,
    float wx, float wy, float ux, float uy, float nax, float nay,
    float dx, float dy, float irx, float iry, float dpx, float dpy)
{
    float2 mc[UNM], mn[UNM];
    #pragma unroll
    for (int i = 0; i < UNM; ++i) mc[i] = __ldg(pm + (size_t)i * C2);

    #pragma unroll 1
    for (int bi = 1; bi < CHUNK / UNM; ++bi) {
        const float2* q = pm + (size_t)bi * UNM * C2;
        #pragma unroll
        for (int i = 0; i < UNM; ++i) mn[i] = __ldg(q + (size_t)i * C2);

        float2* w = po + (size_t)(bi - 1) * UNM * C2;
        #pragma unroll
        for (int i = 0; i < UNM; ++i) {
            float2 o;
            pcen_step<IS_SQRT>(mc[i], ema_x, ema_y, wx, wy, ux, uy,
                               nax, nay, dx, dy, irx, iry, dpx, dpy, o);
            w[(size_t)i * C2] = o;
        }
        #pragma unroll
        for (int i = 0; i < UNM; ++i) mc[i] = mn[i];
    }
    // last batch
    float2* w = po + (size_t)(CHUNK / UNM - 1) * UNM * C2;
    #pragma unroll
    for (int i = 0; i < UNM; ++i) {
        float2 o;
        pcen_step<IS_SQRT>(mc[i], ema_x, ema_y, wx, wy, ux, uy,
                           nax, nay, dx, dy, irx, iry, dpx, dpy, o);
        w[(size_t)i * C2] = o;
    }
}

__global__ void __launch_bounds__(BLOCK, 4)
pcen_kernel(const float* __restrict__ x,
            const float* __restrict__ alpha,
            const float* __restrict__ delta,
            const float* __restrict__ root,
            const float* __restrict__ smooth,
            float* __restrict__ out)
{
    const int ROWS = TB * C2;                       // 2560 float2 lanes
    int gid = blockIdx.x * BLOCK + threadIdx.x;

    int chunk = gid / ROWS;                         // uniform per block (ROWS % BLOCK == 0)
    int rc    = gid - chunk * ROWS;
    int b     = rc / C2;
    int c2    = rc - b * C2;

    // Per-channel-pair constants
    float2 sm = ((const float2*)smooth)[c2];
    float2 al = ((const float2*)alpha)[c2];
    float2 rt = ((const float2*)root)[c2];
    float2 dl = ((const float2*)delta)[c2];
    float wx = fminf(fmaxf(sm.x, 0.0f), 1.0f), wy = fminf(fmaxf(sm.y, 0.0f), 1.0f);
    float ux = 1.0f - wx,                      uy = 1.0f - wy;
    float nax = -fminf(al.x, 1.0f),            nay = -fminf(al.y, 1.0f);
    float rx = fmaxf(rt.x, 1.0f),              ry = fmaxf(rt.y, 1.0f);
    float irx = 1.0f / rx,                     iry = 1.0f / ry;
    float dpx = ex2(irx * lg2(dl.x));          // delta^(1/r), delta > 0 here
    float dpy = ex2(iry * lg2(dl.y));
    bool is_sqrt = (rx == 2.0f) && (ry == 2.0f);

    int s  = chunk * CHUNK;
    int t0 = (chunk == 0) ? 0 : (s - WARM);

    const float2* xp = (const float2*)(x   + ((size_t)b * TT) * TC) + c2;
    float2*       op = (float2*)      (out + ((size_t)b * TT) * TC) + c2;

    float ema_x, ema_y;

    if (chunk == 0) {
        float2 x0 = __ldg(xp);
        ema_x = x0.x; ema_y = x0.y;             // first main update is idempotent
    } else {
        // Warm-up: WARM steps, double-buffered UNW-deep prefetch, no output.
        const float2* p = xp + (size_t)t0 * C2;
        float2 cur[UNW], nxt[UNW];
        #pragma unroll
        for (int i = 0; i < UNW; ++i) cur[i] = __ldg(p + (size_t)i * C2);
        ema_x = cur[0].x; ema_y = cur[0].y;     // seed; first update idempotent

        #pragma unroll 1
        for (int bi = 1; bi < WARM / UNW; ++bi) {
            const float2* q = p + (size_t)bi * UNW * C2;
            #pragma unroll
            for (int i = 0; i < UNW; ++i) nxt[i] = __ldg(q + (size_t)i * C2);
            #pragma unroll
            for (int i = 0; i < UNW; ++i) {
                ema_x = fmaf(ux, ema_x, wx * cur[i].x);
                ema_y = fmaf(uy, ema_y, wy * cur[i].y);
            }
            #pragma unroll
            for (int i = 0; i < UNW; ++i) cur[i] = nxt[i];
        }
        #pragma unroll
        for (int i = 0; i < UNW; ++i) {
            ema_x = fmaf(ux, ema_x, wx * cur[i].x);
            ema_y = fmaf(uy, ema_y, wy * cur[i].y);
        }
    }

    const float2* pm = xp + (size_t)s * C2;
    float2*       po = op + (size_t)s * C2;
    if (is_sqrt)
        main_sweep<true >(pm, po, ema_x, ema_y, wx, wy, ux, uy, nax, nay,
                          dl.x, dl.y, irx, iry, dpx, dpy);
    else
        main_sweep<false>(pm, po, ema_x, ema_y, wx, wy, ux, uy, nax, nay,
                          dl.x, dl.y, irx, iry, dpx, dpy);
}

extern "C" void kernel_launch(void* const* d_in, const int* in_sizes, int n_in,
                              void* d_out, int out_size)
{
    const float* x      = (const float*)d_in[0];
    const float* alpha  = (const float*)d_in[1];
    const float* delta  = (const float*)d_in[2];
    const float* root   = (const float*)d_in[3];
    const float* smooth = (const float*)d_in[4];
    float* out = (float*)d_out;

    const int total = TB * C2 * NCHUNK;        // 81920 threads
    dim3 grid(total / BLOCK);                  // 640 blocks of 128
    pcen_kernel<<<grid, BLOCK>>>(x, alpha, delta, root, smooth, out);
}